// round 4
// baseline (speedup 1.0000x reference)
#include <cuda_runtime.h>
#include <cstdint>

// Problem: input [B=128, C=2, H=512, W=512] fp32.
// out[:,0] = inclusive cumsum along x (last axis, contiguous)
// out[:,1] = inclusive cumsum along y (axis -2, stride W)
// Pure HBM-streaming problem: 256 MiB in + 256 MiB out. Single pass per channel.

#define Bn 128
#define Wn 512

// ---------------------------------------------------------------------------
// Channel 0: x-scan. One warp per row. Each lane owns a float4; 4 iterations
// of 128 elements cover the 512-wide row. Coalesced float4 loads/stores.
// ---------------------------------------------------------------------------
__global__ void __launch_bounds__(256) scan_x_kernel(const float* __restrict__ in,
                                                     float* __restrict__ out) {
    const unsigned gwarp = (blockIdx.x * blockDim.x + threadIdx.x) >> 5;
    const unsigned lane  = threadIdx.x & 31u;
    if (gwarp >= Bn * Wn) return;

    const unsigned b = gwarp >> 9;     // / 512
    const unsigned y = gwarp & 511u;   // % 512

    const size_t base = ((size_t)(b * 2u + 0u) * Wn + y) * Wn;  // channel 0
    const float4* __restrict__ in4  = (const float4*)(in + base);
    float4* __restrict__       out4 = (float4*)(out + base);

    float carry = 0.0f;
#pragma unroll
    for (int it = 0; it < 4; ++it) {
        float4 v = in4[it * 32 + lane];

        // local inclusive scan of the 4 elements
        float s0 = v.x;
        float s1 = s0 + v.y;
        float s2 = s1 + v.z;
        float s3 = s2 + v.w;

        // warp inclusive scan of lane totals
        float incl = s3;
#pragma unroll
        for (int off = 1; off < 32; off <<= 1) {
            float n = __shfl_up_sync(0xffffffffu, incl, off);
            if (lane >= (unsigned)off) incl += n;
        }
        float excl = incl - s3 + carry;

        float4 o;
        o.x = s0 + excl;
        o.y = s1 + excl;
        o.z = s2 + excl;
        o.w = s3 + excl;
        out4[it * 32 + lane] = o;

        // lane 31's inclusive value is the chunk total (carry not yet added)
        carry += __shfl_sync(0xffffffffu, incl, 31);
    }
}

// ---------------------------------------------------------------------------
// Channel 1: y-scan. One thread per column; walk y serially. Adjacent threads
// handle adjacent columns -> every row-step is a fully coalesced 512B warp
// load + store. y unrolled by 8 so 8 independent loads are in flight (MLP=8)
// to hide DRAM latency over the serial FADD carry chain.
// ---------------------------------------------------------------------------
__global__ void __launch_bounds__(128) scan_y_kernel(const float* __restrict__ in,
                                                     float* __restrict__ out) {
    const unsigned x = blockIdx.x * blockDim.x + threadIdx.x;  // column 0..511
    const unsigned b = blockIdx.y;

    const size_t base = ((size_t)(b * 2u + 1u) * Wn) * Wn + x;  // channel 1, y=0
    const float* __restrict__ ip = in + base;
    float* __restrict__       op = out + base;

    float acc = 0.0f;
#pragma unroll 1
    for (int y0 = 0; y0 < Wn; y0 += 8) {
        float v[8];
#pragma unroll
        for (int k = 0; k < 8; ++k)
            v[k] = ip[(size_t)(y0 + k) * Wn];
#pragma unroll
        for (int k = 0; k < 8; ++k) {
            acc += v[k];
            op[(size_t)(y0 + k) * Wn] = acc;
        }
    }
}

extern "C" void kernel_launch(void* const* d_in, const int* in_sizes, int n_in,
                              void* d_out, int out_size) {
    const float* in = (const float*)d_in[0];
    float* out = (float*)d_out;

    // x-scan: 128*512 = 65536 rows, one warp each -> 2,097,152 threads
    {
        const int threads = 256;
        const int warps_needed = Bn * Wn;
        const int blocks = (warps_needed * 32) / threads;  // 8192
        scan_x_kernel<<<blocks, threads>>>(in, out);
    }

    // y-scan: 512 columns per image, 128 threads/block -> 4 blocks per image
    {
        dim3 grid(Wn / 128, Bn);  // (4, 128) = 512 blocks
        scan_y_kernel<<<grid, 128>>>(in, out);
    }
}